// round 1
// baseline (speedup 1.0000x reference)
#include <cuda_runtime.h>
#include <math.h>

#define D      256
#define BROWS  4096
#define NTOT   8192          // 2*BROWS
#define TILE   64
#define BK     32
#define NB     (NTOT / TILE) // 128

// Scratch (no allocations allowed in kernel_launch).
__device__ float g_x[NTOT * D];       // normalized [a; b], row-major, 8 MB
__device__ float g_align[BROWS];      // per-row ||a_i - b_i||^2
__device__ float g_part[NB * NB];     // per-tile partial sums of exp term

// ---------------------------------------------------------------------------
// Deterministic 256-thread block reduction (fixed tree + fixed serial order).
__device__ __forceinline__ float block_reduce_256(float v) {
    __shared__ float sh[8];
    #pragma unroll
    for (int o = 16; o > 0; o >>= 1)
        v += __shfl_down_sync(0xffffffffu, v, o);
    if ((threadIdx.x & 31) == 0) sh[threadIdx.x >> 5] = v;
    __syncthreads();
    if (threadIdx.x == 0) {
        float t = 0.f;
        #pragma unroll
        for (int i = 0; i < 8; i++) t += sh[i];
        sh[0] = t;
    }
    __syncthreads();
    float r = sh[0];
    __syncthreads();   // protect sh before any subsequent call
    return r;
}

// ---------------------------------------------------------------------------
// Kernel 1: L2-normalize both inputs, write concatenated x, per-row align term.
// grid = BROWS blocks, 256 threads (one thread per column).
__global__ __launch_bounds__(256) void normalize_kernel(
    const float* __restrict__ a, const float* __restrict__ b) {
    int row = blockIdx.x;
    int t   = threadIdx.x;

    float va = a[row * D + t];
    float vb = b[row * D + t];

    float sa = block_reduce_256(va * va);
    float sb = block_reduce_256(vb * vb);

    float na = sqrtf(sa);
    float nb = sqrtf(sb);
    float ra = 1.0f / fmaxf(na, 1e-12f);
    float rb = 1.0f / fmaxf(nb, 1e-12f);

    float ah = va * ra;
    float bh = vb * rb;

    g_x[row * D + t]           = ah;
    g_x[(BROWS + row) * D + t] = bh;

    float d  = ah - bh;
    float sd = block_reduce_256(d * d);
    if (t == 0) g_align[row] = sd;
}

// ---------------------------------------------------------------------------
// Kernel 2: tiled Gram over the upper triangle, fused exp + partial reduce.
// grid = (NB, NB); block (by=row tile, bx=col tile); only by<=bx does work.
// 256 threads, 4x4 microtile per thread, BK=32 k-slices, smem transposed
// so the inner loop is 2x LDS.128 + 16 FFMA.
__global__ __launch_bounds__(256) void gram_kernel() {
    const int bx  = blockIdx.x;   // column tile j
    const int by  = blockIdx.y;   // row tile i
    const int tid = threadIdx.x;

    if (by > bx) {                // strict lower triangle: contribute 0
        if (tid == 0) g_part[by * NB + bx] = 0.0f;
        return;
    }

    __shared__ float As[BK][TILE + 4];  // [k][row], row pitch 68 floats (16B-aligned)
    __shared__ float Bs[BK][TILE + 4];

    const int tx = tid & 15;      // 0..15  -> 4 columns each
    const int ty = tid >> 4;      // 0..15  -> 4 rows each

    const float* __restrict__ xa = g_x + (size_t)(by * TILE) * D;
    const float* __restrict__ xb = g_x + (size_t)(bx * TILE) * D;

    float acc[4][4];
    #pragma unroll
    for (int u = 0; u < 4; u++)
        #pragma unroll
        for (int v = 0; v < 4; v++) acc[u][v] = 0.0f;

    for (int k0 = 0; k0 < D; k0 += BK) {
        // Load 64x32 panels (coalesced global reads, transposed smem writes).
        #pragma unroll
        for (int e = 0; e < 8; e++) {
            int idx = tid + e * 256;
            int r   = idx >> 5;   // 0..63
            int c   = idx & 31;   // 0..31
            As[c][r] = xa[r * D + k0 + c];
            Bs[c][r] = xb[r * D + k0 + c];
        }
        __syncthreads();

        #pragma unroll
        for (int k = 0; k < BK; k++) {
            float4 av = *(const float4*)&As[k][ty * 4];
            float4 bv = *(const float4*)&Bs[k][tx * 4];
            acc[0][0] += av.x * bv.x; acc[0][1] += av.x * bv.y;
            acc[0][2] += av.x * bv.z; acc[0][3] += av.x * bv.w;
            acc[1][0] += av.y * bv.x; acc[1][1] += av.y * bv.y;
            acc[1][2] += av.y * bv.z; acc[1][3] += av.y * bv.w;
            acc[2][0] += av.z * bv.x; acc[2][1] += av.z * bv.y;
            acc[2][2] += av.z * bv.z; acc[2][3] += av.z * bv.w;
            acc[3][0] += av.w * bv.x; acc[3][1] += av.w * bv.y;
            acc[3][2] += av.w * bv.z; acc[3][3] += av.w * bv.w;
        }
        __syncthreads();
    }

    // Fused epilogue: e = exp(-2 * max(2 - 2c, 0)) = exp(4*min(c-1, 0)).
    const bool diag = (bx == by);
    const int  i0   = by * TILE + ty * 4;
    const int  j0   = bx * TILE + tx * 4;

    float s = 0.0f;
    #pragma unroll
    for (int u = 0; u < 4; u++) {
        #pragma unroll
        for (int v = 0; v < 4; v++) {
            float c = acc[u][v];
            float e = __expf(4.0f * fminf(c - 1.0f, 0.0f));
            if (!diag || (i0 + u) < (j0 + v)) s += e;
        }
    }

    s = block_reduce_256(s);
    if (tid == 0) g_part[by * NB + bx] = s;
}

// ---------------------------------------------------------------------------
// Kernel 3: deterministic final combine.
__global__ __launch_bounds__(256) void finalize_kernel(float* __restrict__ out) {
    float sa = 0.0f, su = 0.0f;
    for (int i = threadIdx.x; i < BROWS; i += 256)   sa += g_align[i];
    for (int i = threadIdx.x; i < NB * NB; i += 256) su += g_part[i];
    sa = block_reduce_256(sa);
    su = block_reduce_256(su);
    if (threadIdx.x == 0) {
        double align_loss   = (double)sa / (double)BROWS;
        double uniform_loss = 2.0 * (double)su /
                              ((double)NTOT * (double)(NTOT - 1));
        out[0] = (float)(align_loss + uniform_loss);
    }
}

// ---------------------------------------------------------------------------
extern "C" void kernel_launch(void* const* d_in, const int* in_sizes, int n_in,
                              void* d_out, int out_size) {
    const float* a = (const float*)d_in[0];
    const float* b = (const float*)d_in[1];
    float* out = (float*)d_out;

    normalize_kernel<<<BROWS, 256>>>(a, b);
    dim3 grid(NB, NB);
    gram_kernel<<<grid, 256>>>();
    finalize_kernel<<<1, 256>>>(out);
}

// round 3
// speedup vs baseline: 6.2610x; 6.2610x over previous
#include <cuda_runtime.h>
#include <cuda_bf16.h>
#include <cstdint>
#include <math.h>

#define D      256
#define BROWS  4096
#define NTOT   8192
#define TILE   128
#define NB     (NTOT / TILE)          // 64
#define NTILES (NB * (NB + 1) / 2)    // 2080

// ---------------------------------------------------------------------------
// Scratch (allocation-free contract)
__device__ __nv_bfloat16 g_xh[NTOT * D];   // normalized [a;b], bf16 (4 MB)
__device__ float g_align[BROWS];
__device__ float g_part[NTILES];

// ---------------------------------------------------------------------------
__device__ __forceinline__ uint32_t smem_u32(const void* p) {
    uint32_t a;
    asm("{ .reg .u64 t; cvta.to.shared.u64 t, %1; cvt.u32.u64 %0, t; }" : "=r"(a) : "l"(p));
    return a;
}

__device__ __forceinline__ void ldmatrix_x4(uint32_t& r0, uint32_t& r1,
                                            uint32_t& r2, uint32_t& r3, uint32_t addr) {
    asm volatile("ldmatrix.sync.aligned.m8n8.x4.shared.b16 {%0,%1,%2,%3}, [%4];"
                 : "=r"(r0), "=r"(r1), "=r"(r2), "=r"(r3) : "r"(addr));
}

__device__ __forceinline__ void mma_16816(float* c, const uint32_t* a, const uint32_t* b) {
    asm volatile(
        "mma.sync.aligned.m16n8k16.row.col.f32.bf16.bf16.f32 "
        "{%0,%1,%2,%3}, {%4,%5,%6,%7}, {%8,%9}, {%0,%1,%2,%3};"
        : "+f"(c[0]), "+f"(c[1]), "+f"(c[2]), "+f"(c[3])
        : "r"(a[0]), "r"(a[1]), "r"(a[2]), "r"(a[3]), "r"(b[0]), "r"(b[1]));
}

// ---------------------------------------------------------------------------
__device__ __forceinline__ float block_reduce_256(float v) {
    __shared__ float sh[8];
    #pragma unroll
    for (int o = 16; o > 0; o >>= 1) v += __shfl_down_sync(0xffffffffu, v, o);
    if ((threadIdx.x & 31) == 0) sh[threadIdx.x >> 5] = v;
    __syncthreads();
    if (threadIdx.x == 0) {
        float t = 0.f;
        #pragma unroll
        for (int i = 0; i < 8; i++) t += sh[i];
        sh[0] = t;
    }
    __syncthreads();
    float r = sh[0];
    __syncthreads();
    return r;
}

// ---------------------------------------------------------------------------
// Kernel 1: L2-normalize, write bf16 concat x, per-row align term.
__global__ __launch_bounds__(256) void normalize_kernel(
    const float* __restrict__ a, const float* __restrict__ b) {
    int row = blockIdx.x;
    int t   = threadIdx.x;

    float va = a[row * D + t];
    float vb = b[row * D + t];

    float sa = block_reduce_256(va * va);
    float sb = block_reduce_256(vb * vb);

    float ra = 1.0f / fmaxf(sqrtf(sa), 1e-12f);
    float rb = 1.0f / fmaxf(sqrtf(sb), 1e-12f);

    float ah = va * ra;
    float bh = vb * rb;

    g_xh[row * D + t]           = __float2bfloat16(ah);
    g_xh[(BROWS + row) * D + t] = __float2bfloat16(bh);

    float d  = ah - bh;
    float sd = block_reduce_256(d * d);
    if (t == 0) g_align[row] = sd;
}

// ---------------------------------------------------------------------------
// Kernel 2: HMMA Gram tile + fused exp epilogue. One CTA per upper-tri tile.
// Smem: As/Bs 128 rows x 512 B, 16B-chunk XOR swizzle: chunk' = chunk ^ (row&7).
extern __shared__ char gsm[];
#define AS_OFF 0
#define BS_OFF 65536
#define SMEM_TOTAL 131072

__global__ __launch_bounds__(256, 1) void gram_kernel() {
    const int tid  = threadIdx.x;
    const int wid  = tid >> 5;
    const int lane = tid & 31;
    const uint32_t smem_base = smem_u32(gsm);

    // tile index -> (by, bx), by <= bx
    int by = 0, rem = blockIdx.x;
    while (rem >= NB - by) { rem -= NB - by; by++; }
    const int bx   = by + rem;
    const bool diag = (bx == by);

    const __nv_bfloat16* __restrict__ xa = g_xh + (size_t)(by * TILE) * D;
    const __nv_bfloat16* __restrict__ xb = g_xh + (size_t)(bx * TILE) * D;

    // ---- Load tiles to swizzled smem: 4096 16B-chunks per tile ----
    #pragma unroll
    for (int e = 0; e < 16; e++) {
        int i = tid + e * 256;
        int r = i >> 5;          // 0..127
        int c = i & 31;          // 16B chunk 0..31
        int sw = (c ^ (r & 7)) << 4;
        uint4 v = *(const uint4*)(xa + (size_t)r * D + c * 8);
        *(uint4*)(gsm + AS_OFF + r * 512 + sw) = v;
        if (!diag) {
            uint4 w = *(const uint4*)(xb + (size_t)r * D + c * 8);
            *(uint4*)(gsm + BS_OFF + r * 512 + sw) = w;
        }
    }
    __syncthreads();

    // ---- Warp tiling: 2 (m) x 4 (n) warps; warp tile 64x32 ----
    const int warp_m = wid >> 2;        // 0..1  -> 64 rows
    const int warp_n = wid & 3;         // 0..3  -> 32 cols
    const uint32_t bs_base = smem_base + (diag ? AS_OFF : BS_OFF);

    // Per-thread ldmatrix address components (row fixed per thread).
    // A (x4, one 16x16 m-tile): row = warp_m*64 + mt*16 + (lane&15); chunk = 2ks + (lane>>4)
    uint32_t a_base[4], a_rx[4];
    #pragma unroll
    for (int mt = 0; mt < 4; mt++) {
        int r = warp_m * 64 + mt * 16 + (lane & 15);
        a_base[mt] = smem_base + AS_OFF + r * 512;
        a_rx[mt]   = r & 7;
    }
    const uint32_t a_c0 = lane >> 4;    // 0/1

    // B (x4, two 16x8 n-tiles): row = warp_n*32 + nt2*16 + (lane>>4)*8 + (lane&7)
    //                           chunk = 2ks + ((lane>>3)&1)
    uint32_t b_base[2], b_rx[2];
    #pragma unroll
    for (int nt2 = 0; nt2 < 2; nt2++) {
        int r = warp_n * 32 + nt2 * 16 + (lane >> 4) * 8 + (lane & 7);
        b_base[nt2] = bs_base + r * 512;
        b_rx[nt2]   = r & 7;
    }
    const uint32_t b_c0 = (lane >> 3) & 1;

    float acc[4][4][4];                 // [mt][nt][reg]
    #pragma unroll
    for (int mt = 0; mt < 4; mt++)
        #pragma unroll
        for (int nt = 0; nt < 4; nt++)
            #pragma unroll
            for (int q = 0; q < 4; q++) acc[mt][nt][q] = 0.0f;

    #pragma unroll
    for (int ks = 0; ks < 16; ks++) {
        uint32_t af[4][4];
        #pragma unroll
        for (int mt = 0; mt < 4; mt++) {
            uint32_t addr = a_base[mt] + (((2 * ks + a_c0) ^ a_rx[mt]) << 4);
            ldmatrix_x4(af[mt][0], af[mt][1], af[mt][2], af[mt][3], addr);
        }
        uint32_t bf[4][2];
        #pragma unroll
        for (int nt2 = 0; nt2 < 2; nt2++) {
            uint32_t addr = b_base[nt2] + (((2 * ks + b_c0) ^ b_rx[nt2]) << 4);
            uint32_t r0, r1, r2, r3;
            ldmatrix_x4(r0, r1, r2, r3, addr);
            bf[nt2 * 2 + 0][0] = r0; bf[nt2 * 2 + 0][1] = r1;
            bf[nt2 * 2 + 1][0] = r2; bf[nt2 * 2 + 1][1] = r3;
        }
        #pragma unroll
        for (int mt = 0; mt < 4; mt++)
            #pragma unroll
            for (int nt = 0; nt < 4; nt++)
                mma_16816(acc[mt][nt], af[mt], bf[nt]);
    }

    // ---- Fused epilogue: e = exp(4*min(c-1,0)), strict-upper mask on diag ----
    const int gid = lane >> 2;          // row group 0..7
    const int tig = lane & 3;           // col pair 0..3
    float s = 0.0f;
    #pragma unroll
    for (int mt = 0; mt < 4; mt++) {
        const int r0 = warp_m * 64 + mt * 16 + gid;   // tile-local rows r0, r0+8
        #pragma unroll
        for (int nt = 0; nt < 4; nt++) {
            const int c0 = warp_n * 32 + nt * 8 + tig * 2;
            #pragma unroll
            for (int q = 0; q < 4; q++) {
                const int rr = r0 + ((q >> 1) << 3);
                const int cc = c0 + (q & 1);
                float v = acc[mt][nt][q];
                float e = __expf(4.0f * fminf(v - 1.0f, 0.0f));
                if (!diag || cc > rr) s += e;
            }
        }
    }

    s = block_reduce_256(s);
    if (tid == 0) g_part[blockIdx.x] = s;
}

// ---------------------------------------------------------------------------
// Kernel 3: deterministic final combine.
__global__ __launch_bounds__(256) void finalize_kernel(float* __restrict__ out) {
    float sa = 0.0f, su = 0.0f;
    for (int i = threadIdx.x; i < BROWS; i += 256)  sa += g_align[i];
    for (int i = threadIdx.x; i < NTILES; i += 256) su += g_part[i];
    sa = block_reduce_256(sa);
    su = block_reduce_256(su);
    if (threadIdx.x == 0) {
        double align_loss   = (double)sa / (double)BROWS;
        double uniform_loss = 2.0 * (double)su / ((double)NTOT * (double)(NTOT - 1));
        out[0] = (float)(align_loss + uniform_loss);
    }
}

// ---------------------------------------------------------------------------
extern "C" void kernel_launch(void* const* d_in, const int* in_sizes, int n_in,
                              void* d_out, int out_size) {
    const float* a = (const float*)d_in[0];
    const float* b = (const float*)d_in[1];
    float* out = (float*)d_out;

    static bool attr_set = false;
    if (!attr_set) {
        cudaFuncSetAttribute(gram_kernel,
                             cudaFuncAttributeMaxDynamicSharedMemorySize, SMEM_TOTAL);
        attr_set = true;
    }

    normalize_kernel<<<BROWS, 256>>>(a, b);
    gram_kernel<<<NTILES, 256, SMEM_TOTAL>>>();
    finalize_kernel<<<1, 256>>>(out);
}